// round 1
// baseline (speedup 1.0000x reference)
#include <cuda_runtime.h>
#include <math.h>

#define NN 4096
#define MM 20
#define HH 16
#define NX 32
#define NY 18
#define NLAB 3
#define NCELL (NLAB*NX*NY)
#define CAP 64
#define PI_F 3.14159274101257324f
#define QPI_F 0.785398185253143311f
#define COND 0.2f
#define IOUT 0.3f

// ---------- device scratch (no allocations allowed) ----------
__device__ int            g_order[NN];
__device__ float          g_b7[NN*7];
__device__ float          g_bx1[NN], g_by1[NN], g_bx2[NN], g_by2[NN], g_area[NN];
__device__ int            g_cell[NN];
__device__ int            g_cellcnt[NCELL];
__device__ int            g_cellstart[NCELL];
__device__ int            g_cellptr[NCELL];
__device__ unsigned short g_celllist[NN];
__device__ unsigned short g_pred[NN*CAP];
__device__ unsigned short g_succ[NN*CAP];
__device__ int            g_npred[NN], g_nsucc[NN];
__device__ unsigned char  g_valid[NN];
__device__ unsigned char  g_status[NN];   // 0=unknown 1=kept 2=suppressed
__device__ int            g_suppby[NN];

// ---------- 1) stable descending sort by (valid? score : -inf), index tiebreak ----------
__global__ __launch_bounds__(1024) void k_sort(const float* __restrict__ scores) {
    __shared__ unsigned long long s[NN];
    int t = threadIdx.x;
    for (int c = t; c < NCELL; c += 1024) g_cellcnt[c] = 0;  // reset accumulators
    for (int i = t; i < NN; i += 1024) {
        float f = scores[i];
        unsigned k;
        if (f > COND) {
            unsigned b = __float_as_uint(f);
            unsigned u = (b & 0x80000000u) ? ~b : (b | 0x80000000u);
            k = ~u;                       // ascending k == descending f
        } else {
            k = 0xFFFFFFFFu;              // all invalid tie -> stable by index
        }
        s[i] = ((unsigned long long)k << 32) | (unsigned)i;
    }
    __syncthreads();
    for (int size = 2; size <= NN; size <<= 1) {
        for (int stride = size >> 1; stride > 0; stride >>= 1) {
            for (int i = t; i < NN; i += 1024) {
                int ixj = i ^ stride;
                if (ixj > i) {
                    unsigned long long a = s[i], b = s[ixj];
                    bool up = ((i & size) == 0);
                    if ((a > b) == up) { s[i] = b; s[ixj] = a; }
                }
            }
            __syncthreads();
        }
    }
    for (int i = t; i < NN; i += 1024) g_order[i] = (int)(s[i] & 0xFFFFFFFFu);
}

// ---------- 2) gather into sorted order, bev boxes, cell histogram, baseline outputs ----------
__global__ void k_gather(const float* __restrict__ pb, const float* __restrict__ ps,
                         const int* __restrict__ pl, float* __restrict__ out) {
    int i = blockIdx.x * blockDim.x + threadIdx.x;
    if (i >= NN) return;
    int idx = g_order[i];
    float b[9];
    #pragma unroll
    for (int c = 0; c < 9; c++) b[c] = pb[idx*9 + c];
    #pragma unroll
    for (int c = 0; c < 7; c++) { g_b7[i*7 + c] = b[c]; out[i*9 + c] = b[c]; }
    out[i*9 + 7] = b[7];
    out[i*9 + 8] = b[8];
    float sc = ps[idx];
    out[NN*9  + i] = sc;
    int lab = pl[idx];
    out[NN*10 + i] = (float)lab;
    bool valid = sc > COND;
    g_valid[i]  = valid ? 1 : 0;
    g_status[i] = valid ? 0 : 2;

    float h   = b[6];
    float ang = h - floorf(h / PI_F + 0.5f) * PI_F;
    bool  sw  = fabsf(ang) >= QPI_F;
    float dx  = sw ? b[4] : b[3];
    float dy  = sw ? b[3] : b[4];
    g_bx1[i] = b[0] - dx * 0.5f;
    g_by1[i] = b[1] - dy * 0.5f;
    g_bx2[i] = b[0] + dx * 0.5f;
    g_by2[i] = b[1] + dy * 0.5f;
    g_area[i] = dx * dy;

    int cx = (int)floorf((b[0] + 70.0f) * (1.0f / 4.5f)); cx = min(max(cx, 0), NX-1);
    int cy = (int)floorf((b[1] + 40.0f) * (1.0f / 4.5f)); cy = min(max(cy, 0), NY-1);
    int cell = (lab * NY + cy) * NX + cx;
    g_cell[i] = cell;
    atomicAdd(&g_cellcnt[cell], 1);
}

// ---------- 3) exclusive scan over cell counts ----------
__global__ __launch_bounds__(1024) void k_cellscan() {
    __shared__ int pairsum[1024];
    int t = threadIdx.x;
    int a = (2*t     < NCELL) ? g_cellcnt[2*t]     : 0;
    int b = (2*t + 1 < NCELL) ? g_cellcnt[2*t + 1] : 0;
    pairsum[t] = a + b;
    __syncthreads();
    for (int off = 1; off < 1024; off <<= 1) {
        int v = (t >= off) ? pairsum[t - off] : 0;
        __syncthreads();
        pairsum[t] += v;
        __syncthreads();
    }
    int excl = (t == 0) ? 0 : pairsum[t - 1];
    if (2*t < NCELL)     { g_cellstart[2*t]     = excl;     g_cellptr[2*t]     = excl; }
    if (2*t + 1 < NCELL) { g_cellstart[2*t + 1] = excl + a; g_cellptr[2*t + 1] = excl + a; }
}

// ---------- 4) fill cell lists ----------
__global__ void k_fill() {
    int i = blockIdx.x * blockDim.x + threadIdx.x;
    if (i >= NN) return;
    int pos = atomicAdd(&g_cellptr[g_cell[i]], 1);
    g_celllist[pos] = (unsigned short)i;
}

// ---------- 5) build overlap predecessor/successor lists (same label, iou>0.3) ----------
__global__ void k_build() {
    int i = blockIdx.x * blockDim.x + threadIdx.x;
    if (i >= NN) return;
    float ax1 = g_bx1[i], ay1 = g_by1[i], ax2 = g_bx2[i], ay2 = g_by2[i], aa = g_area[i];
    int cell = g_cell[i];
    int cx = cell % NX, cy = (cell / NX) % NY, lab = cell / (NX * NY);
    int np = 0, ns = 0;
    for (int dy = -1; dy <= 1; dy++) {
        int yy = cy + dy; if (yy < 0 || yy >= NY) continue;
        for (int dx = -1; dx <= 1; dx++) {
            int xx = cx + dx; if (xx < 0 || xx >= NX) continue;
            int c2 = (lab * NY + yy) * NX + xx;
            int s0 = g_cellstart[c2], s1 = s0 + g_cellcnt[c2];
            for (int p = s0; p < s1; p++) {
                int j = g_celllist[p];
                if (j == i) continue;
                float ix = fminf(ax2, g_bx2[j]) - fmaxf(ax1, g_bx1[j]);
                float iy = fminf(ay2, g_by2[j]) - fmaxf(ay1, g_by1[j]);
                float inter = fmaxf(ix, 0.0f) * fmaxf(iy, 0.0f);
                float uni   = aa + g_area[j] - inter;
                if (inter > IOUT * fmaxf(uni, 1e-6f)) {
                    if (j < i) { if (np < CAP) g_pred[i*CAP + np++] = (unsigned short)j; }
                    else       { if (ns < CAP) g_succ[i*CAP + ns++] = (unsigned short)j; }
                }
            }
        }
    }
    // insertion-sort succ ascending (cluster member order)
    for (int a = 1; a < ns; a++) {
        unsigned short v = g_succ[i*CAP + a];
        int b = a - 1;
        while (b >= 0 && g_succ[i*CAP + b] > v) { g_succ[i*CAP + b + 1] = g_succ[i*CAP + b]; b--; }
        g_succ[i*CAP + b + 1] = v;
    }
    g_npred[i] = np;
    g_nsucc[i] = ns;
}

// ---------- 6) keep-set fixpoint (monotone chaotic relaxation; races are benign) ----------
__global__ __launch_bounds__(1024) void k_fix(float* __restrict__ out) {
    __shared__ unsigned char st_[NN];
    __shared__ int done;
    volatile unsigned char* st = st_;
    int t = threadIdx.x;
    for (int i = t; i < NN; i += 1024) st_[i] = g_status[i];
    __syncthreads();
    for (int round = 0; round < NN; round++) {
        if (t == 0) done = 1;
        __syncthreads();
        for (int i = t; i < NN; i += 1024) {
            if (st[i] == 0) {
                int np = g_npred[i];
                bool anyK = false, allS = true;
                for (int p = 0; p < np; p++) {
                    unsigned char s = st[g_pred[i*CAP + p]];
                    anyK |= (s == 1);
                    allS &= (s == 2);
                }
                if (anyK)      st[i] = 2;
                else if (allS) st[i] = 1;
                else           done = 0;
            }
        }
        __syncthreads();
        if (done) break;
    }
    for (int i = t; i < NN; i += 1024) {
        unsigned char s = st_[i];
        g_status[i] = s;
        out[NN*11 + i] = (s == 1) ? 1.0f : 0.0f;   // keep flags
    }
}

// ---------- 7) suppressor = min kept overlapping predecessor ----------
__global__ void k_suppby() {
    int i = blockIdx.x * blockDim.x + threadIdx.x;
    if (i >= NN) return;
    unsigned char s = g_status[i];
    if (s == 1) { g_suppby[i] = i; return; }
    if (!g_valid[i]) { g_suppby[i] = -1; return; }
    int np = g_npred[i];
    int best = 0x7FFFFFFF;
    for (int p = 0; p < np; p++) {
        int q = g_pred[i*CAP + p];
        if (g_status[q] == 1 && q < best) best = q;
    }
    g_suppby[i] = best;
}

// ---------- 8) merge MLP for kept clusters with count>1 ----------
__global__ void k_merge(const float* __restrict__ w1, const float* __restrict__ b1,
                        const float* __restrict__ w2, const float* __restrict__ b2,
                        const float* __restrict__ w3, const float* __restrict__ b3,
                        float* __restrict__ out) {
    __shared__ float s_w1[MM*HH], s_w2[HH*HH], s_w3[HH], s_b1[HH], s_b2[HH], s_b3;
    int t = threadIdx.x;
    for (int k = t; k < MM*HH; k += blockDim.x) s_w1[k] = w1[k];
    for (int k = t; k < HH*HH; k += blockDim.x) s_w2[k] = w2[k];
    if (t < HH) { s_w3[t] = w3[t]; s_b1[t] = b1[t]; s_b2[t] = b2[t]; }
    if (t == 0) s_b3 = b3[0];
    __syncthreads();

    int i = blockIdx.x * blockDim.x + t;
    if (i >= NN) return;
    if (g_status[i] != 1) return;

    int ns = g_nsucc[i];
    int mem[MM];
    mem[0] = i;
    int cnt = 1, total = 1;
    for (int a = 0; a < ns; a++) {
        int j = g_succ[i*CAP + a];
        if (g_suppby[j] == i) { total++; if (cnt < MM) mem[cnt++] = j; }
    }
    if (total <= 1) return;   // baseline copy already written

    float ob[7];
    for (int c = 0; c < 7; c++) {
        float h1[HH];
        #pragma unroll
        for (int h = 0; h < HH; h++) h1[h] = s_b1[h];
        for (int m = 0; m < cnt; m++) {
            float xv = g_b7[mem[m]*7 + c];
            #pragma unroll
            for (int h = 0; h < HH; h++) h1[h] += xv * s_w1[m*HH + h];
        }
        #pragma unroll
        for (int h = 0; h < HH; h++) h1[h] = fmaxf(h1[h], 0.0f);
        float h2[HH];
        #pragma unroll
        for (int q = 0; q < HH; q++) h2[q] = s_b2[q];
        #pragma unroll
        for (int h = 0; h < HH; h++) {
            float v = h1[h];
            #pragma unroll
            for (int q = 0; q < HH; q++) h2[q] += v * s_w2[h*HH + q];
        }
        float acc = s_b3;
        #pragma unroll
        for (int q = 0; q < HH; q++) acc += fmaxf(h2[q], 0.0f) * s_w3[q];
        ob[c] = acc;
    }
    ob[3] = fmaxf(ob[3], 1e-5f);
    ob[4] = fmaxf(ob[4], 1e-5f);
    ob[5] = fmaxf(ob[5], 1e-5f);
    #pragma unroll
    for (int c = 0; c < 7; c++) out[i*9 + c] = ob[c];
}

extern "C" void kernel_launch(void* const* d_in, const int* in_sizes, int n_in,
                              void* d_out, int out_size) {
    const float* pb = (const float*)d_in[0];
    const float* ps = (const float*)d_in[1];
    const int*   pl = (const int*)  d_in[2];
    const float* w1 = (const float*)d_in[3];
    const float* b1 = (const float*)d_in[4];
    const float* w2 = (const float*)d_in[5];
    const float* b2 = (const float*)d_in[6];
    const float* w3 = (const float*)d_in[7];
    const float* b3 = (const float*)d_in[8];
    float* out = (float*)d_out;

    k_sort<<<1, 1024>>>(ps);
    k_gather<<<16, 256>>>(pb, ps, pl, out);
    k_cellscan<<<1, 1024>>>();
    k_fill<<<16, 256>>>();
    k_build<<<32, 128>>>();
    k_fix<<<1, 1024>>>(out);
    k_suppby<<<16, 256>>>();
    k_merge<<<32, 128>>>(w1, b1, w2, b2, w3, b3, out);
}